// round 12
// baseline (speedup 1.0000x reference)
#include <cuda_runtime.h>
#include <cuda_bf16.h>
#include <cuda_fp16.h>
#include <math.h>
#include <float.h>
#include <stdint.h>

#define BB 4
#define LL 2048
#define DD 256

// ---------------- device scratch (allocation-free rule) ----------------
__device__ float g_c[DD];                              // bv @ Wo + bo
__device__ __half g_WTf16[DD * DD];                    // (Wv@Wo)^T fp16
__device__ __half g_valf16[BB * LL * DD];              // value fp16 [8192][256]
__device__ __half g_V2Tf16[DD * BB * LL];              // V2^T fp16 [256][8192]

// ---------------- helpers ----------------
__device__ __forceinline__ uint32_t smem_u32(const void* p) {
    uint32_t a;
    asm("{ .reg .u64 t; cvta.to.shared.u64 t, %1; cvt.u32.u64 %0, t; }" : "=r"(a) : "l"(p));
    return a;
}
#define CP_ASYNC16(sm, g) \
    asm volatile("cp.async.cg.shared.global [%0], [%1], 16;" :: "r"(sm), "l"(g))
#define CP_COMMIT() asm volatile("cp.async.commit_group;")
#define CP_WAITG(n) asm volatile("cp.async.wait_group %0;" :: "n"(n))

#define LDSM4(r0, r1, r2, r3, addr)                                            \
    asm volatile("ldmatrix.sync.aligned.m8n8.x4.shared.b16 {%0,%1,%2,%3}, [%4];" \
                 : "=r"(r0), "=r"(r1), "=r"(r2), "=r"(r3) : "r"(addr))

#define MMA_F16(d, a, b0, b1)                                                    \
    asm volatile("mma.sync.aligned.m16n8k16.row.col.f32.f16.f16.f32 "            \
                 "{%0,%1,%2,%3},{%4,%5,%6,%7},{%8,%9},{%0,%1,%2,%3};"            \
                 : "+f"((d)[0]), "+f"((d)[1]), "+f"((d)[2]), "+f"((d)[3])        \
                 : "r"((a)[0]), "r"((a)[1]), "r"((a)[2]), "r"((a)[3]),           \
                   "r"(b0), "r"(b1))

#define SWX(row, colb) ((row) * 128 + ((colb) ^ (((row) & 7) << 4)))

// ---------------------------------------------------------------------------
// Kernel 1 (heterogeneous):
//   blocks [0,32):      WT rows — block computes 8 rows of W = Wv@Wo, thread j
//                       owns column j with 8 independent accumulators (ILP=8,
//                       coalesced Wo loads).
//   block 32:           bias c = bv@Wo + bo (4-way partial sums).
//   blocks [33,33+2048): value fp32 -> fp16.
// ---------------------------------------------------------------------------
__global__ void k_pre(const float* __restrict__ Wv, const float* __restrict__ Wo,
                      const float* __restrict__ bv, const float* __restrict__ bo,
                      const float4* __restrict__ v) {
    const int blk = blockIdx.x;
    const int j = threadIdx.x;
    if (blk < 32) {
        __shared__ float sWv[8][DD];
        const int i0 = blk * 8;
#pragma unroll
        for (int r = 0; r < 8; r++) sWv[r][j] = Wv[(i0 + r) * DD + j];
        __syncthreads();
        float acc[8] = {};
#pragma unroll 4
        for (int k = 0; k < DD; k++) {
            float wo = Wo[k * DD + j];
#pragma unroll
            for (int r = 0; r < 8; r++) acc[r] += sWv[r][k] * wo;
        }
#pragma unroll
        for (int r = 0; r < 8; r++)
            g_WTf16[j * DD + i0 + r] = __float2half(acc[r]);
    } else if (blk == 32) {
        float s0 = 0.f, s1 = 0.f, s2 = 0.f, s3 = 0.f;
#pragma unroll 4
        for (int k = 0; k < DD; k += 4) {
            s0 += bv[k + 0] * Wo[(k + 0) * DD + j];
            s1 += bv[k + 1] * Wo[(k + 1) * DD + j];
            s2 += bv[k + 2] * Wo[(k + 2) * DD + j];
            s3 += bv[k + 3] * Wo[(k + 3) * DD + j];
        }
        g_c[j] = (s0 + s1) + (s2 + s3) + bo[j];
    } else {
        int i = (blk - 33) * 256 + j;
        float4 x = v[i];
        __half2 a = __floats2half2_rn(x.x, x.y);
        __half2 b = __floats2half2_rn(x.z, x.w);
        uint2 pk = {*(uint32_t*)&a, *(uint32_t*)&b};
        ((uint2*)g_valf16)[i] = pk;
    }
}

// ---------------------------------------------------------------------------
// Kernel 2: projection GEMM  V2T = WT @ value^T  (fp16, 128x128 tile)
// ---------------------------------------------------------------------------
#define PKC 64
#define PTILE (128 * 128)
#define PSTAGE (2 * PTILE)
#define PNSTG 3
#define PSMEM (PNSTG * PSTAGE)

__device__ __forceinline__ void pv_load(
    uint32_t st, const __half* A, const __half* B,
    int lda, int ldb, int m0, int n0, int k0, int t) {
#pragma unroll
    for (int i = 0; i < 4; i++) {
        int idx = t + i * 256;
        int row = idx >> 3, seg = idx & 7;
        CP_ASYNC16(st + SWX(row, seg * 16),
                   A + (size_t)(m0 + row) * lda + k0 + seg * 8);
        CP_ASYNC16(st + PTILE + SWX(row, seg * 16),
                   B + (size_t)(n0 + row) * ldb + k0 + seg * 8);
    }
    CP_COMMIT();
}

__global__ void __launch_bounds__(256, 2)
k_proj(const __half* __restrict__ A, const __half* __restrict__ B,
       __half* __restrict__ Ch, int lda, int ldb, int ldc, int Ktot) {
    extern __shared__ char smem[];
    const uint32_t sbase = smem_u32(smem);
    const int t = threadIdx.x;
    const int lane = t & 31, wid = t >> 5;
    const int wm = wid >> 2, wn = wid & 3;
    const int n0 = blockIdx.x * 128;
    const int m0 = blockIdx.y * 128;
    const int NC = Ktot / PKC;

    float acc[4][4][4] = {};

    pv_load(sbase, A, B, lda, ldb, m0, n0, 0, t);
    pv_load(sbase + PSTAGE, A, B, lda, ldb, m0, n0, PKC, t);

    const int lrow = lane & 15;
    const int lcolb = (lane >> 4) * 16;

    for (int c = 0; c < NC; c++) {
        if (c + 2 < NC) {
            pv_load(sbase + ((c + 2) % PNSTG) * PSTAGE, A, B, lda, ldb,
                    m0, n0, (c + 2) * PKC, t);
            CP_WAITG(2);
        } else if (c + 1 < NC) {
            CP_WAITG(1);
        } else {
            CP_WAITG(0);
        }
        __syncthreads();
        uint32_t st = sbase + (c % PNSTG) * PSTAGE;
#pragma unroll
        for (int ks = 0; ks < 4; ks++) {
            const uint32_t kcb = ks * 32 + lcolb;
            uint32_t ah[4][4], bh[2][4];
#pragma unroll
            for (int mf = 0; mf < 4; mf++) {
                int row = wm * 64 + mf * 16 + lrow;
                LDSM4(ah[mf][0], ah[mf][1], ah[mf][2], ah[mf][3], st + SWX(row, kcb));
            }
#pragma unroll
            for (int nf2 = 0; nf2 < 2; nf2++) {
                int row = wn * 32 + nf2 * 16 + lrow;
                LDSM4(bh[nf2][0], bh[nf2][1], bh[nf2][2], bh[nf2][3],
                      st + PTILE + SWX(row, kcb));
            }
#pragma unroll
            for (int nf2 = 0; nf2 < 2; nf2++)
#pragma unroll
                for (int mf = 0; mf < 4; mf++) {
                    MMA_F16(acc[mf][nf2 * 2],     ah[mf], bh[nf2][0], bh[nf2][2]);
                    MMA_F16(acc[mf][nf2 * 2 + 1], ah[mf], bh[nf2][1], bh[nf2][3]);
                }
        }
        __syncthreads();
    }

    const int g = lane >> 2, tc = lane & 3;
#pragma unroll
    for (int mf = 0; mf < 4; mf++) {
        int r = m0 + wm * 64 + mf * 16 + g;
#pragma unroll
        for (int nf = 0; nf < 4; nf++) {
            int cidx = n0 + wn * 32 + nf * 8 + 2 * tc;
            *(__half2*)(Ch + (size_t)r * ldc + cidx) =
                __floats2half2_rn(acc[mf][nf][0], acc[mf][nf][1]);
            *(__half2*)(Ch + (size_t)(r + 8) * ldc + cidx) =
                __floats2half2_rn(acc[mf][nf][2], acc[mf][nf][3]);
        }
    }
}

// ---------------------------------------------------------------------------
// Kernel 3 (FUSED): masked exp + PV GEMM + normalize + bias, one pass.
// ---------------------------------------------------------------------------
#define FM 64
#define FKC 64
#define FNC (LL / FKC)                   // 32
#define FIN_PITCH 272                    // 256B data + 16B skew
#define FIN_TILE (FM * FIN_PITCH)        // 17408
#define FIN_STAGE (3 * FIN_TILE)         // 52224 (atten,mask,pad)
#define FV2_TILE (256 * 128)             // 32768
#define FSTAGE (FIN_STAGE + FV2_TILE)    // 84992
#define FP_TILE (FM * 128)               // 8192
#define FOFF_IN(s)  ((s) * FSTAGE)
#define FOFF_V2(s)  ((s) * FSTAGE + FIN_STAGE)
#define FOFF_P(s)   (2 * FSTAGE + (s) * FP_TILE)
#define FOFF_SUM    (2 * FSTAGE + 2 * FP_TILE)
#define FSMEM       (FOFF_SUM + 256)     // 186624

__device__ __forceinline__ void f_load(
    uint32_t sb, const float* at, const float* mk, const int* pd,
    const __half* v2t, int s, int b, int m0, int k0, int t) {
#pragma unroll
    for (int i = 0; i < 4; i++) {
        int idx = t + i * 256;
        int row = idx >> 4, seg = idx & 15;
        size_t g = ((size_t)b * LL + m0 + row) * LL + k0 + seg * 4;
        uint32_t d = sb + FOFF_IN(s) + row * FIN_PITCH + seg * 16;
        CP_ASYNC16(d, at + g);
        CP_ASYNC16(d + FIN_TILE, mk + g);
        CP_ASYNC16(d + 2 * FIN_TILE, (const float*)pd + g);
    }
#pragma unroll
    for (int i = 0; i < 8; i++) {
        int idx = t + i * 256;
        int row = idx >> 3, seg = idx & 7;
        CP_ASYNC16(sb + FOFF_V2(s) + SWX(row, seg * 16),
                   v2t + (size_t)row * (BB * LL) + (size_t)b * LL + k0 + seg * 8);
    }
    CP_COMMIT();
}

__global__ void __launch_bounds__(256, 1)
k_fused(const float* __restrict__ atten, const float* __restrict__ mask,
        const int* __restrict__ pad, const __half* __restrict__ v2t,
        float* __restrict__ out) {
    extern __shared__ char smem[];
    const uint32_t sb = smem_u32(smem);
    const int t = threadIdx.x;
    const int lane = t & 31, wid = t >> 5;
    const int m0 = blockIdx.x * FM;
    const int b  = blockIdx.y;

    float* rowsum = (float*)(smem + FOFF_SUM);
    if (t < FM) rowsum[t] = 0.f;

    f_load(sb, atten, mask, pad, v2t, 0, b, m0, 0, t);
    f_load(sb, atten, mask, pad, v2t, 1, b, m0, FKC, t);

    float acc[4][4][4] = {};
    const int r  = t >> 2;
    const int cg = t & 3;
    const int lrow = lane & 15;
    const int lcolb = (lane >> 4) * 16;

    for (int c = 0; c < FNC; c++) {
        if (c + 1 < FNC) { CP_WAITG(1); } else { CP_WAITG(0); }
        __syncthreads();

        // ---- exp phase ----
        {
            const char* ib = smem + FOFF_IN(c & 1) + r * FIN_PITCH + cg * 64;
            float e[16];
            float part = 0.f;
#pragma unroll
            for (int q = 0; q < 4; q++) {
                float4 a  = *(const float4*)(ib + q * 16);
                float4 mk = *(const float4*)(ib + FIN_TILE + q * 16);
                int4   p  = *(const int4*)(ib + 2 * FIN_TILE + q * 16);
                float e0 = (mk.x < 0.5f || p.x == 0) ? 0.f : __expf(a.x);
                float e1 = (mk.y < 0.5f || p.y == 0) ? 0.f : __expf(a.y);
                float e2 = (mk.z < 0.5f || p.z == 0) ? 0.f : __expf(a.z);
                float e3 = (mk.w < 0.5f || p.w == 0) ? 0.f : __expf(a.w);
                e[q * 4 + 0] = e0; e[q * 4 + 1] = e1;
                e[q * 4 + 2] = e2; e[q * 4 + 3] = e3;
                part += (e0 + e1) + (e2 + e3);
            }
            part += __shfl_xor_sync(0xffffffffu, part, 1);
            part += __shfl_xor_sync(0xffffffffu, part, 2);
            if (cg == 0) rowsum[r] += part;
            uint32_t pb = sb + FOFF_P(c & 1);
            uint32_t h[8];
#pragma unroll
            for (int q = 0; q < 8; q++) {
                __half2 hh = __floats2half2_rn(e[q * 2], e[q * 2 + 1]);
                h[q] = *(uint32_t*)&hh;
            }
            uint32_t colb = cg * 32;
            asm volatile("st.shared.v4.b32 [%0], {%1,%2,%3,%4};"
                :: "r"(pb + SWX(r, colb)), "r"(h[0]), "r"(h[1]), "r"(h[2]), "r"(h[3]));
            asm volatile("st.shared.v4.b32 [%0], {%1,%2,%3,%4};"
                :: "r"(pb + SWX(r, colb + 16)), "r"(h[4]), "r"(h[5]), "r"(h[6]), "r"(h[7]));
        }
        __syncthreads();

        // ---- MMA phase ----
        {
            uint32_t pb = sb + FOFF_P(c & 1);
            uint32_t vb = sb + FOFF_V2(c & 1);
#pragma unroll
            for (int kt = 0; kt < 4; kt++) {
                const uint32_t kcb = kt * 32 + lcolb;
                uint32_t ah[4][4], bh[2][4];
#pragma unroll
                for (int mf = 0; mf < 4; mf++)
                    LDSM4(ah[mf][0], ah[mf][1], ah[mf][2], ah[mf][3],
                          pb + SWX(mf * 16 + lrow, kcb));
#pragma unroll
                for (int nf2 = 0; nf2 < 2; nf2++)
                    LDSM4(bh[nf2][0], bh[nf2][1], bh[nf2][2], bh[nf2][3],
                          vb + SWX(wid * 32 + nf2 * 16 + lrow, kcb));
#pragma unroll
                for (int nf2 = 0; nf2 < 2; nf2++)
#pragma unroll
                    for (int mf = 0; mf < 4; mf++) {
                        MMA_F16(acc[mf][nf2 * 2],     ah[mf], bh[nf2][0], bh[nf2][2]);
                        MMA_F16(acc[mf][nf2 * 2 + 1], ah[mf], bh[nf2][1], bh[nf2][3]);
                    }
            }
        }
        __syncthreads();

        if (c + 2 < FNC)
            f_load(sb, atten, mask, pad, v2t, c & 1, b, m0, (c + 2) * FKC, t);
    }

    // ---- epilogue ----
    const int g = lane >> 2, tc = lane & 3;
#pragma unroll
    for (int mf = 0; mf < 4; mf++) {
        int rl0 = mf * 16 + g;
        float inv0 = 1.0f / rowsum[rl0];
        float inv1 = 1.0f / rowsum[rl0 + 8];
        size_t o0 = ((size_t)b * LL + m0 + rl0) * DD;
#pragma unroll
        for (int nf = 0; nf < 4; nf++) {
            int col = wid * 32 + nf * 8 + tc * 2;
            float b0 = g_c[col], b1 = g_c[col + 1];
            *(float2*)(out + o0 + col) =
                {acc[mf][nf][0] * inv0 + b0, acc[mf][nf][1] * inv0 + b1};
            *(float2*)(out + o0 + (size_t)8 * DD + col) =
                {acc[mf][nf][2] * inv1 + b0, acc[mf][nf][3] * inv1 + b1};
        }
    }
}

// ---------------------------------------------------------------------------
extern "C" void kernel_launch(void* const* d_in, const int* in_sizes, int n_in,
                              void* d_out, int out_size) {
    const float* atten = (const float*)d_in[0];
    const float* value = (const float*)d_in[1];
    const float* mask  = (const float*)d_in[2];
    const int*   pad   = (const int*)d_in[3];
    const float* Wv    = (const float*)d_in[4];
    const float* bv    = (const float*)d_in[5];
    const float* Wo    = (const float*)d_in[6];
    const float* bo    = (const float*)d_in[7];
    float* out = (float*)d_out;

    void *pWT, *pVal, *pV2;
    cudaGetSymbolAddress(&pWT, g_WTf16);
    cudaGetSymbolAddress(&pVal, g_valf16);
    cudaGetSymbolAddress(&pV2, g_V2Tf16);

    cudaFuncSetAttribute(k_proj, cudaFuncAttributeMaxDynamicSharedMemorySize, PSMEM);
    cudaFuncSetAttribute(k_fused, cudaFuncAttributeMaxDynamicSharedMemorySize, FSMEM);

    // 0: WT fp16 + bias + value->fp16 (heterogeneous, ILP-shaped wc)
    k_pre<<<33 + 2048, 256>>>(Wv, Wo, bv, bo, (const float4*)value);
    // 1: V2T = WT @ value^T (M=256, N=8192, K=256)
    k_proj<<<dim3((BB * LL) / 128, DD / 128, 1), 256, PSMEM>>>(
        (const __half*)pWT, (const __half*)pVal, (__half*)pV2,
        DD, DD, BB * LL, DD);
    // 2: fused masked-softmax + PV + bias
    k_fused<<<dim3(LL / FM, BB), 256, FSMEM>>>(
        atten, mask, pad, (const __half*)pV2, out);
}

// round 13
// speedup vs baseline: 1.1582x; 1.1582x over previous
#include <cuda_runtime.h>
#include <cuda_bf16.h>
#include <cuda_fp16.h>
#include <math.h>
#include <float.h>
#include <stdint.h>

#define BB 4
#define LL 2048
#define DD 256

// ---------------- device scratch (allocation-free rule) ----------------
__device__ float g_c[DD];                              // bv @ Wo + bo
__device__ __half g_WTf16[DD * DD];                    // (Wv@Wo)^T fp16
__device__ __half g_valf16[BB * LL * DD];              // value fp16 [8192][256]
__device__ __half g_V2Tf16[DD * BB * LL];              // V2^T fp16 [256][8192]

// ---------------- helpers ----------------
__device__ __forceinline__ uint32_t smem_u32(const void* p) {
    uint32_t a;
    asm("{ .reg .u64 t; cvta.to.shared.u64 t, %1; cvt.u32.u64 %0, t; }" : "=r"(a) : "l"(p));
    return a;
}
#define CP_ASYNC16(sm, g) \
    asm volatile("cp.async.cg.shared.global [%0], [%1], 16;" :: "r"(sm), "l"(g))
#define CP_COMMIT() asm volatile("cp.async.commit_group;")
#define CP_WAITG(n) asm volatile("cp.async.wait_group %0;" :: "n"(n))

#define LDSM4(r0, r1, r2, r3, addr)                                            \
    asm volatile("ldmatrix.sync.aligned.m8n8.x4.shared.b16 {%0,%1,%2,%3}, [%4];" \
                 : "=r"(r0), "=r"(r1), "=r"(r2), "=r"(r3) : "r"(addr))

#define MMA_F16(d, a, b0, b1)                                                    \
    asm volatile("mma.sync.aligned.m16n8k16.row.col.f32.f16.f16.f32 "            \
                 "{%0,%1,%2,%3},{%4,%5,%6,%7},{%8,%9},{%0,%1,%2,%3};"            \
                 : "+f"((d)[0]), "+f"((d)[1]), "+f"((d)[2]), "+f"((d)[3])        \
                 : "r"((a)[0]), "r"((a)[1]), "r"((a)[2]), "r"((a)[3]),           \
                   "r"(b0), "r"(b1))

#define SWX(row, colb) ((row) * 128 + ((colb) ^ (((row) & 7) << 4)))

// ---------------------------------------------------------------------------
// Kernel 1 (heterogeneous):
//   blocks [0,33):  W rows / bias via cp.async-staged Wo chunks (latency
//                   hidden; old version had 256 serial DRAM loads -> 26us).
//                   blk<32: 8 rows of W=Wv@Wo. blk==32: c = bv@Wo + bo.
//   blocks [33,33+2048): value fp32 -> fp16.
// ---------------------------------------------------------------------------
__global__ void k_pre(const float* __restrict__ Wv, const float* __restrict__ Wo,
                      const float* __restrict__ bv, const float* __restrict__ bo,
                      const float4* __restrict__ v) {
    const int blk = blockIdx.x;
    const int j = threadIdx.x;
    if (blk < 33) {
        __shared__ float sW[8][DD];            // Wv rows (or bv in sW[0])
        __shared__ float sWo[2][16][DD];       // staged Wo chunks (2 x 16KB)
        const bool isbias = (blk == 32);
        const int i0 = blk * 8;
        if (isbias) {
            sW[0][j] = bv[j];
        } else {
#pragma unroll
            for (int r = 0; r < 8; r++) sW[r][j] = Wv[(i0 + r) * DD + j];
        }
        const uint32_t swo = smem_u32(&sWo[0][0][0]);

        // stage chunk 0 (16 rows x 1KB = 16KB; 4 x 16B per thread)
#pragma unroll
        for (int i = 0; i < 4; i++) {
            int idx = j + i * 256;
            int row = idx >> 6, seg = idx & 63;
            CP_ASYNC16(swo + (row * DD + seg * 4) * 4, Wo + row * DD + seg * 4);
        }
        CP_COMMIT();
        __syncthreads();

        float acc[8] = {};
        for (int c = 0; c < 16; c++) {
            if (c + 1 < 16) {
                uint32_t dst = swo + ((c + 1) & 1) * 16 * DD * 4;
                const float* src = Wo + (c + 1) * 16 * DD;
#pragma unroll
                for (int i = 0; i < 4; i++) {
                    int idx = j + i * 256;
                    int row = idx >> 6, seg = idx & 63;
                    CP_ASYNC16(dst + (row * DD + seg * 4) * 4, src + row * DD + seg * 4);
                }
                CP_COMMIT();
                CP_WAITG(1);
            } else {
                CP_WAITG(0);
            }
            __syncthreads();
            const int s = c & 1;
            if (isbias) {
#pragma unroll
                for (int kk = 0; kk < 16; kk++)
                    acc[kk & 3] += sW[0][c * 16 + kk] * sWo[s][kk][j];
            } else {
#pragma unroll
                for (int kk = 0; kk < 16; kk++) {
                    float wo = sWo[s][kk][j];
                    int k = c * 16 + kk;
#pragma unroll
                    for (int r = 0; r < 8; r++) acc[r] += sW[r][k] * wo;
                }
            }
            __syncthreads();
        }
        if (isbias) {
            g_c[j] = (acc[0] + acc[1]) + (acc[2] + acc[3]) + bo[j];
        } else {
#pragma unroll
            for (int r = 0; r < 8; r++)
                g_WTf16[j * DD + i0 + r] = __float2half(acc[r]);
        }
    } else {
        int i = (blk - 33) * 256 + j;
        float4 x = v[i];
        __half2 a = __floats2half2_rn(x.x, x.y);
        __half2 b = __floats2half2_rn(x.z, x.w);
        uint2 pk = {*(uint32_t*)&a, *(uint32_t*)&b};
        ((uint2*)g_valf16)[i] = pk;
    }
}

// ---------------------------------------------------------------------------
// Kernel 2: projection GEMM  V2T = WT @ value^T  (fp16, 128x128 tile)
// ---------------------------------------------------------------------------
#define PKC 64
#define PTILE (128 * 128)
#define PSTAGE (2 * PTILE)
#define PNSTG 3
#define PSMEM (PNSTG * PSTAGE)

__device__ __forceinline__ void pv_load(
    uint32_t st, const __half* A, const __half* B,
    int lda, int ldb, int m0, int n0, int k0, int t) {
#pragma unroll
    for (int i = 0; i < 4; i++) {
        int idx = t + i * 256;
        int row = idx >> 3, seg = idx & 7;
        CP_ASYNC16(st + SWX(row, seg * 16),
                   A + (size_t)(m0 + row) * lda + k0 + seg * 8);
        CP_ASYNC16(st + PTILE + SWX(row, seg * 16),
                   B + (size_t)(n0 + row) * ldb + k0 + seg * 8);
    }
    CP_COMMIT();
}

__global__ void __launch_bounds__(256, 2)
k_proj(const __half* __restrict__ A, const __half* __restrict__ B,
       __half* __restrict__ Ch, int lda, int ldb, int ldc, int Ktot) {
    extern __shared__ char smem[];
    const uint32_t sbase = smem_u32(smem);
    const int t = threadIdx.x;
    const int lane = t & 31, wid = t >> 5;
    const int wm = wid >> 2, wn = wid & 3;
    const int n0 = blockIdx.x * 128;
    const int m0 = blockIdx.y * 128;
    const int NC = Ktot / PKC;

    float acc[4][4][4] = {};

    pv_load(sbase, A, B, lda, ldb, m0, n0, 0, t);
    pv_load(sbase + PSTAGE, A, B, lda, ldb, m0, n0, PKC, t);

    const int lrow = lane & 15;
    const int lcolb = (lane >> 4) * 16;

    for (int c = 0; c < NC; c++) {
        if (c + 2 < NC) {
            pv_load(sbase + ((c + 2) % PNSTG) * PSTAGE, A, B, lda, ldb,
                    m0, n0, (c + 2) * PKC, t);
            CP_WAITG(2);
        } else if (c + 1 < NC) {
            CP_WAITG(1);
        } else {
            CP_WAITG(0);
        }
        __syncthreads();
        uint32_t st = sbase + (c % PNSTG) * PSTAGE;
#pragma unroll
        for (int ks = 0; ks < 4; ks++) {
            const uint32_t kcb = ks * 32 + lcolb;
            uint32_t ah[4][4], bh[2][4];
#pragma unroll
            for (int mf = 0; mf < 4; mf++) {
                int row = wm * 64 + mf * 16 + lrow;
                LDSM4(ah[mf][0], ah[mf][1], ah[mf][2], ah[mf][3], st + SWX(row, kcb));
            }
#pragma unroll
            for (int nf2 = 0; nf2 < 2; nf2++) {
                int row = wn * 32 + nf2 * 16 + lrow;
                LDSM4(bh[nf2][0], bh[nf2][1], bh[nf2][2], bh[nf2][3],
                      st + PTILE + SWX(row, kcb));
            }
#pragma unroll
            for (int nf2 = 0; nf2 < 2; nf2++)
#pragma unroll
                for (int mf = 0; mf < 4; mf++) {
                    MMA_F16(acc[mf][nf2 * 2],     ah[mf], bh[nf2][0], bh[nf2][2]);
                    MMA_F16(acc[mf][nf2 * 2 + 1], ah[mf], bh[nf2][1], bh[nf2][3]);
                }
        }
        __syncthreads();
    }

    const int g = lane >> 2, tc = lane & 3;
#pragma unroll
    for (int mf = 0; mf < 4; mf++) {
        int r = m0 + wm * 64 + mf * 16 + g;
#pragma unroll
        for (int nf = 0; nf < 4; nf++) {
            int cidx = n0 + wn * 32 + nf * 8 + 2 * tc;
            *(__half2*)(Ch + (size_t)r * ldc + cidx) =
                __floats2half2_rn(acc[mf][nf][0], acc[mf][nf][1]);
            *(__half2*)(Ch + (size_t)(r + 8) * ldc + cidx) =
                __floats2half2_rn(acc[mf][nf][2], acc[mf][nf][3]);
        }
    }
}

// ---------------------------------------------------------------------------
// Kernel 3 (FUSED): masked exp + PV GEMM + normalize + bias, one pass.
// ---------------------------------------------------------------------------
#define FM 64
#define FKC 64
#define FNC (LL / FKC)                   // 32
#define FIN_PITCH 272                    // 256B data + 16B skew
#define FIN_TILE (FM * FIN_PITCH)        // 17408
#define FIN_STAGE (3 * FIN_TILE)         // 52224 (atten,mask,pad)
#define FV2_TILE (256 * 128)             // 32768
#define FSTAGE (FIN_STAGE + FV2_TILE)    // 84992
#define FP_TILE (FM * 128)               // 8192
#define FOFF_IN(s)  ((s) * FSTAGE)
#define FOFF_V2(s)  ((s) * FSTAGE + FIN_STAGE)
#define FOFF_P(s)   (2 * FSTAGE + (s) * FP_TILE)
#define FOFF_SUM    (2 * FSTAGE + 2 * FP_TILE)
#define FSMEM       (FOFF_SUM + 256)     // 186624

__device__ __forceinline__ void f_load(
    uint32_t sb, const float* at, const float* mk, const int* pd,
    const __half* v2t, int s, int b, int m0, int k0, int t) {
#pragma unroll
    for (int i = 0; i < 4; i++) {
        int idx = t + i * 256;
        int row = idx >> 4, seg = idx & 15;
        size_t g = ((size_t)b * LL + m0 + row) * LL + k0 + seg * 4;
        uint32_t d = sb + FOFF_IN(s) + row * FIN_PITCH + seg * 16;
        CP_ASYNC16(d, at + g);
        CP_ASYNC16(d + FIN_TILE, mk + g);
        CP_ASYNC16(d + 2 * FIN_TILE, (const float*)pd + g);
    }
#pragma unroll
    for (int i = 0; i < 8; i++) {
        int idx = t + i * 256;
        int row = idx >> 3, seg = idx & 7;
        CP_ASYNC16(sb + FOFF_V2(s) + SWX(row, seg * 16),
                   v2t + (size_t)row * (BB * LL) + (size_t)b * LL + k0 + seg * 8);
    }
    CP_COMMIT();
}

__global__ void __launch_bounds__(256, 1)
k_fused(const float* __restrict__ atten, const float* __restrict__ mask,
        const int* __restrict__ pad, const __half* __restrict__ v2t,
        float* __restrict__ out) {
    extern __shared__ char smem[];
    const uint32_t sb = smem_u32(smem);
    const int t = threadIdx.x;
    const int lane = t & 31, wid = t >> 5;
    const int m0 = blockIdx.x * FM;
    const int b  = blockIdx.y;

    float* rowsum = (float*)(smem + FOFF_SUM);
    if (t < FM) rowsum[t] = 0.f;

    f_load(sb, atten, mask, pad, v2t, 0, b, m0, 0, t);
    f_load(sb, atten, mask, pad, v2t, 1, b, m0, FKC, t);

    float acc[4][4][4] = {};
    const int r  = t >> 2;
    const int cg = t & 3;
    const int lrow = lane & 15;
    const int lcolb = (lane >> 4) * 16;

    for (int c = 0; c < FNC; c++) {
        if (c + 1 < FNC) { CP_WAITG(1); } else { CP_WAITG(0); }
        __syncthreads();

        // ---- exp phase ----
        {
            const char* ib = smem + FOFF_IN(c & 1) + r * FIN_PITCH + cg * 64;
            float e[16];
            float part = 0.f;
#pragma unroll
            for (int q = 0; q < 4; q++) {
                float4 a  = *(const float4*)(ib + q * 16);
                float4 mk = *(const float4*)(ib + FIN_TILE + q * 16);
                int4   p  = *(const int4*)(ib + 2 * FIN_TILE + q * 16);
                float e0 = (mk.x < 0.5f || p.x == 0) ? 0.f : __expf(a.x);
                float e1 = (mk.y < 0.5f || p.y == 0) ? 0.f : __expf(a.y);
                float e2 = (mk.z < 0.5f || p.z == 0) ? 0.f : __expf(a.z);
                float e3 = (mk.w < 0.5f || p.w == 0) ? 0.f : __expf(a.w);
                e[q * 4 + 0] = e0; e[q * 4 + 1] = e1;
                e[q * 4 + 2] = e2; e[q * 4 + 3] = e3;
                part += (e0 + e1) + (e2 + e3);
            }
            part += __shfl_xor_sync(0xffffffffu, part, 1);
            part += __shfl_xor_sync(0xffffffffu, part, 2);
            if (cg == 0) rowsum[r] += part;
            uint32_t pb = sb + FOFF_P(c & 1);
            uint32_t h[8];
#pragma unroll
            for (int q = 0; q < 8; q++) {
                __half2 hh = __floats2half2_rn(e[q * 2], e[q * 2 + 1]);
                h[q] = *(uint32_t*)&hh;
            }
            uint32_t colb = cg * 32;
            asm volatile("st.shared.v4.b32 [%0], {%1,%2,%3,%4};"
                :: "r"(pb + SWX(r, colb)), "r"(h[0]), "r"(h[1]), "r"(h[2]), "r"(h[3]));
            asm volatile("st.shared.v4.b32 [%0], {%1,%2,%3,%4};"
                :: "r"(pb + SWX(r, colb + 16)), "r"(h[4]), "r"(h[5]), "r"(h[6]), "r"(h[7]));
        }
        __syncthreads();

        // ---- MMA phase ----
        {
            uint32_t pb = sb + FOFF_P(c & 1);
            uint32_t vb = sb + FOFF_V2(c & 1);
#pragma unroll
            for (int kt = 0; kt < 4; kt++) {
                const uint32_t kcb = kt * 32 + lcolb;
                uint32_t ah[4][4], bh[2][4];
#pragma unroll
                for (int mf = 0; mf < 4; mf++)
                    LDSM4(ah[mf][0], ah[mf][1], ah[mf][2], ah[mf][3],
                          pb + SWX(mf * 16 + lrow, kcb));
#pragma unroll
                for (int nf2 = 0; nf2 < 2; nf2++)
                    LDSM4(bh[nf2][0], bh[nf2][1], bh[nf2][2], bh[nf2][3],
                          vb + SWX(wid * 32 + nf2 * 16 + lrow, kcb));
#pragma unroll
                for (int nf2 = 0; nf2 < 2; nf2++)
#pragma unroll
                    for (int mf = 0; mf < 4; mf++) {
                        MMA_F16(acc[mf][nf2 * 2],     ah[mf], bh[nf2][0], bh[nf2][2]);
                        MMA_F16(acc[mf][nf2 * 2 + 1], ah[mf], bh[nf2][1], bh[nf2][3]);
                    }
            }
        }
        __syncthreads();

        if (c + 2 < FNC)
            f_load(sb, atten, mask, pad, v2t, c & 1, b, m0, (c + 2) * FKC, t);
    }

    // ---- epilogue ----
    const int g = lane >> 2, tc = lane & 3;
#pragma unroll
    for (int mf = 0; mf < 4; mf++) {
        int rl0 = mf * 16 + g;
        float inv0 = 1.0f / rowsum[rl0];
        float inv1 = 1.0f / rowsum[rl0 + 8];
        size_t o0 = ((size_t)b * LL + m0 + rl0) * DD;
#pragma unroll
        for (int nf = 0; nf < 4; nf++) {
            int col = wid * 32 + nf * 8 + tc * 2;
            float b0 = g_c[col], b1 = g_c[col + 1];
            *(float2*)(out + o0 + col) =
                {acc[mf][nf][0] * inv0 + b0, acc[mf][nf][1] * inv0 + b1};
            *(float2*)(out + o0 + (size_t)8 * DD + col) =
                {acc[mf][nf][2] * inv1 + b0, acc[mf][nf][3] * inv1 + b1};
        }
    }
}

// ---------------------------------------------------------------------------
extern "C" void kernel_launch(void* const* d_in, const int* in_sizes, int n_in,
                              void* d_out, int out_size) {
    const float* atten = (const float*)d_in[0];
    const float* value = (const float*)d_in[1];
    const float* mask  = (const float*)d_in[2];
    const int*   pad   = (const int*)d_in[3];
    const float* Wv    = (const float*)d_in[4];
    const float* bv    = (const float*)d_in[5];
    const float* Wo    = (const float*)d_in[6];
    const float* bo    = (const float*)d_in[7];
    float* out = (float*)d_out;

    void *pWT, *pVal, *pV2;
    cudaGetSymbolAddress(&pWT, g_WTf16);
    cudaGetSymbolAddress(&pVal, g_valf16);
    cudaGetSymbolAddress(&pV2, g_V2Tf16);

    cudaFuncSetAttribute(k_proj, cudaFuncAttributeMaxDynamicSharedMemorySize, PSMEM);
    cudaFuncSetAttribute(k_fused, cudaFuncAttributeMaxDynamicSharedMemorySize, FSMEM);

    // 0: WT fp16 + bias + value->fp16 (staged-Wo latency-hidden wc)
    k_pre<<<33 + 2048, 256>>>(Wv, Wo, bv, bo, (const float4*)value);
    // 1: V2T = WT @ value^T (M=256, N=8192, K=256)
    k_proj<<<dim3((BB * LL) / 128, DD / 128, 1), 256, PSMEM>>>(
        (const __half*)pWT, (const __half*)pVal, (__half*)pV2,
        DD, DD, BB * LL, DD);
    // 2: fused masked-softmax + PV + bias
    k_fused<<<dim3(LL / FM, BB), 256, FSMEM>>>(
        atten, mask, pad, (const __half*)pV2, out);
}